// round 13
// baseline (speedup 1.0000x reference)
#include <cuda_runtime.h>
#include <cstdint>

// Problem constants (fixed by reference setup_inputs)
#define NB  8      // batch
#define CCH 512    // channels
#define NH  8      // heads
#define DD  64     // head dim
#define LL  64     // token length
#define CTK 256    // token channels
#define HW  16384  // 128*128 pixels

#define EP2 258    // epilogue buffer stride per d-pair row (floats): 128px*2 + 2 pad

// Scratch (device globals — no allocations allowed).
// Stored PRE-SWIZZLED in the packed-pair rotated layout the attn kernel uses:
//   element (row, col) -> row*64 + 2*((4*(col>>3) + (col&3) + 4*row)&31) + ((col>>2)&1)
// g_k: row=l, col=d (K/8, tf32-rounded).  g_v: row=d, col=l (V, tf32-rounded).
__device__ __align__(16) float g_k[NB * CCH * LL];
__device__ __align__(16) float g_v[NB * CCH * LL];

__device__ __forceinline__ uint32_t f2tf32(float x) {
    uint32_t r;
    asm("cvt.rn.tf32.f32 %0, %1;" : "=r"(r) : "f"(x));
    return r;
}

// m16n8k8 tf32 HMMA (base-target instruction, works at compute_103)
__device__ __forceinline__ void mma_tf32(float* c,
                                         uint32_t a0, uint32_t a1, uint32_t a2, uint32_t a3,
                                         uint32_t b0, uint32_t b1) {
    asm volatile(
        "mma.sync.aligned.m16n8k8.row.col.f32.tf32.tf32.f32 "
        "{%0,%1,%2,%3}, {%4,%5,%6,%7}, {%8,%9}, {%0,%1,%2,%3};"
        : "+f"(c[0]), "+f"(c[1]), "+f"(c[2]), "+f"(c[3])
        : "r"(a0), "r"(a1), "r"(a2), "r"(a3), "r"(b0), "r"(b1));
}

// ============================================================================
// Kernel 1: fused V/K projections (1x1 conv, K=256). Measured-best structure;
// outputs written directly in the rotated packed-pair layout.
// Grid: 8*512 blocks, 64 threads (thread = l).
// ============================================================================
__global__ void vk_kernel(const float* __restrict__ token,
                          const float* __restrict__ Wv, const float* __restrict__ bv,
                          const float* __restrict__ Wk, const float* __restrict__ bk) {
    __shared__ float wv_s[CTK];
    __shared__ float wk_s[CTK];
    const int o = blockIdx.x & (CCH - 1);
    const int n = blockIdx.x >> 9;
    const int l = threadIdx.x;

#pragma unroll
    for (int i = 0; i < 4; i++) {
        wv_s[l + 64 * i] = Wv[o * CTK + l + 64 * i];
        wk_s[l + 64 * i] = Wk[o * CTK + l + 64 * i];
    }
    __syncthreads();

    const float* tok = token + n * (CTK * LL) + l;
    float av0 = 0.f, av1 = 0.f, ak0 = 0.f, ak1 = 0.f;
#pragma unroll 8
    for (int ct = 0; ct < CTK; ct += 2) {
        float t0 = tok[ct * LL];
        float t1 = tok[(ct + 1) * LL];
        av0 = fmaf(wv_s[ct],     t0, av0);
        ak0 = fmaf(wk_s[ct],     t0, ak0);
        av1 = fmaf(wv_s[ct + 1], t1, av1);
        ak1 = fmaf(wk_s[ct + 1], t1, ak1);
    }
    float av = av0 + av1 + bv[o];
    float ak = (ak0 + ak1 + bk[o]) * 0.125f;  // 1/sqrt(C/h) = 1/8

    const int h = o >> 6, d = o & 63;
    const int slice = (n * NH + h) * (DD * LL);
    const int ka = l * 64 + 2 * ((4 * (d >> 3) + (d & 3) + 4 * l) & 31) + ((d >> 2) & 1);
    const int va = d * 64 + 2 * ((4 * (l >> 3) + (l & 3) + 4 * d) & 31) + ((l >> 2) & 1);
    g_k[slice + ka] = __uint_as_float(f2tf32(ak));
    g_v[slice + va] = __uint_as_float(f2tf32(av));
}

// ============================================================================
// Kernel 2: mma.sync tf32 attention, M=32 per warp, one 128-px tile per CTA.
// CTA = 128 threads = 128 pixels of one (n,h); grid = 64 * 128 = 8192.
// Pixel permutation: MMA row r of m-tile T <-> local px 4*(r&7)+(r>>3)+2T,
// so the 4 A-regs at one d-column are one float4 (LDG.128; full 128B lines),
// and GEMM2 D-regs (c0,c1)=(px,d),(px,d+1) pair into float2 stores in a
// d-pair-major epilogue buffer (bank-conflict-free: 2qid+8gid per phase).
// Epilogue READ is float2-per-lane (8B-aligned, conflict-free) + scalar
// coalesced gmem residual/store — the R12 float4 read was misaligned (EP2=258
// is 2 mod 4), this is the fix.
// ============================================================================
__global__ __launch_bounds__(128, 3)
void attn_kernel(const float* __restrict__ feature, float* __restrict__ out) {
    __shared__ __align__(16) float sm[32 * EP2];    // K/V staging, then epi buffer
    float* ks = sm;                                  // [64 l][64 d] packed-pair rotated
    float* vs = sm + 4096;                           // [64 d][64 l] packed-pair rotated

    const int tid  = threadIdx.x;
    const int lane = tid & 31;
    const int warp = tid >> 5;
    const int gid  = lane >> 2;   // fragment row group
    const int qid  = lane & 3;    // fragment col group
    const int nh   = blockIdx.x >> 7;
    const int tile = blockIdx.x & 127;

    // ---- stage K/V: plain float4 copy (layout already rotated in gmem) ----
    {
        const float4* gk4 = reinterpret_cast<const float4*>(g_k) + nh * 1024;
        const float4* gv4 = reinterpret_cast<const float4*>(g_v) + nh * 1024;
        float4* ks4 = reinterpret_cast<float4*>(ks);
        float4* vs4 = reinterpret_cast<float4*>(vs);
#pragma unroll
        for (int i = 0; i < 8; i++) {
            int idx = tid + 128 * i;
            ks4[idx] = gk4[idx];
            vs4[idx] = gv4[idx];
        }
    }

    const float* f = feature + nh * (DD * HW) + tile * 128 + warp * 32;
    const int rot = (qid + 4 * gid) & 31;

    __syncthreads();

    // ---- GEMM1: acc[2 m-tiles][8 n-tiles][4]; Q frags via LDG.128 (px perm) ----
    float acc[64];
#pragma unroll
    for (int i = 0; i < 64; i++) acc[i] = 0.f;
#pragma unroll
    for (int kt = 0; kt < 8; kt++) {
        // px 4gid..4gid+3 = (T0 row gid), (T0 row gid+8), (T1 row gid), (T1 row gid+8)
        float4 q0 = *reinterpret_cast<const float4*>(f + (8 * kt + qid) * HW + 4 * gid);
        float4 q1 = *reinterpret_cast<const float4*>(f + (8 * kt + qid + 4) * HW + 4 * gid);
        uint32_t a[2][4];
        a[0][0] = f2tf32(q0.x);  a[0][1] = f2tf32(q0.y);   // T0: rows gid, gid+8, col qid
        a[1][0] = f2tf32(q0.z);  a[1][1] = f2tf32(q0.w);   // T1
        a[0][2] = f2tf32(q1.x);  a[0][3] = f2tf32(q1.y);   // col qid+4
        a[1][2] = f2tf32(q1.z);  a[1][3] = f2tf32(q1.w);
        const int c2 = (4 * kt + rot) & 31;
#pragma unroll
        for (int j = 0; j < 8; j++) {
            float2 b = *reinterpret_cast<const float2*>(&ks[(8 * j + gid) * 64 + 2 * c2]);
            uint32_t b0 = __float_as_uint(b.x), b1 = __float_as_uint(b.y);
            mma_tf32(&acc[4 * j],      a[0][0], a[0][1], a[0][2], a[0][3], b0, b1);
            mma_tf32(&acc[32 + 4 * j], a[1][0], a[1][1], a[1][2], a[1][3], b0, b1);
        }
    }

    // ---- softmax per m-tile (rows gid via c0/c1, gid+8 via c2/c3) ----
#pragma unroll
    for (int T = 0; T < 2; T++) {
        float* ac = acc + 32 * T;
        float m0 = -1e30f, m1 = -1e30f;
#pragma unroll
        for (int j = 0; j < 8; j++) {
            m0 = fmaxf(m0, fmaxf(ac[4 * j + 0], ac[4 * j + 1]));
            m1 = fmaxf(m1, fmaxf(ac[4 * j + 2], ac[4 * j + 3]));
        }
        m0 = fmaxf(m0, __shfl_xor_sync(0xffffffffu, m0, 1));
        m0 = fmaxf(m0, __shfl_xor_sync(0xffffffffu, m0, 2));
        m1 = fmaxf(m1, __shfl_xor_sync(0xffffffffu, m1, 1));
        m1 = fmaxf(m1, __shfl_xor_sync(0xffffffffu, m1, 2));
        float s0 = 0.f, s1 = 0.f;
#pragma unroll
        for (int j = 0; j < 8; j++) {
            ac[4 * j + 0] = __expf(ac[4 * j + 0] - m0); s0 += ac[4 * j + 0];
            ac[4 * j + 1] = __expf(ac[4 * j + 1] - m0); s0 += ac[4 * j + 1];
            ac[4 * j + 2] = __expf(ac[4 * j + 2] - m1); s1 += ac[4 * j + 2];
            ac[4 * j + 3] = __expf(ac[4 * j + 3] - m1); s1 += ac[4 * j + 3];
        }
        s0 += __shfl_xor_sync(0xffffffffu, s0, 1);
        s0 += __shfl_xor_sync(0xffffffffu, s0, 2);
        s1 += __shfl_xor_sync(0xffffffffu, s1, 1);
        s1 += __shfl_xor_sync(0xffffffffu, s1, 2);
        const float inv0 = __frcp_rn(s0);
        const float inv1 = __frcp_rn(s1);
#pragma unroll
        for (int j = 0; j < 8; j++) {
            ac[4 * j + 0] = __uint_as_float(f2tf32(ac[4 * j + 0] * inv0));
            ac[4 * j + 1] = __uint_as_float(f2tf32(ac[4 * j + 1] * inv0));
            ac[4 * j + 2] = __uint_as_float(f2tf32(ac[4 * j + 2] * inv1));
            ac[4 * j + 3] = __uint_as_float(f2tf32(ac[4 * j + 3] * inv1));
        }
    }

    // ---- remap coef D-frag -> A-frag in place (row-preserving; perm-safe) ----
    {
        const int s0 = 4 * gid + (qid >> 1);
        const int s1 = s0 + 2;
        const bool odd = qid & 1;
#pragma unroll
        for (int T = 0; T < 2; T++) {
            float* ac = acc + 32 * T;
#pragma unroll
            for (int t = 0; t < 8; t++) {
                float v0 = __shfl_sync(0xffffffffu, ac[4 * t + 0], s0);
                float v1 = __shfl_sync(0xffffffffu, ac[4 * t + 1], s0);
                float v2 = __shfl_sync(0xffffffffu, ac[4 * t + 2], s0);
                float v3 = __shfl_sync(0xffffffffu, ac[4 * t + 3], s0);
                float w0 = __shfl_sync(0xffffffffu, ac[4 * t + 0], s1);
                float w1 = __shfl_sync(0xffffffffu, ac[4 * t + 1], s1);
                float w2 = __shfl_sync(0xffffffffu, ac[4 * t + 2], s1);
                float w3 = __shfl_sync(0xffffffffu, ac[4 * t + 3], s1);
                ac[4 * t + 0] = odd ? v1 : v0;
                ac[4 * t + 1] = odd ? v3 : v2;
                ac[4 * t + 2] = odd ? w1 : w0;
                ac[4 * t + 3] = odd ? w3 : w2;
            }
        }
    }

    // ---- GEMM2: pr[2][8 d-tiles][4] = coef * V^T ----
    float pr[64];
#pragma unroll
    for (int i = 0; i < 64; i++) pr[i] = 0.f;
#pragma unroll
    for (int t = 0; t < 8; t++) {
        const int c2 = (4 * t + rot) & 31;
#pragma unroll
        for (int j = 0; j < 8; j++) {
            float2 b = *reinterpret_cast<const float2*>(&vs[(8 * j + gid) * 64 + 2 * c2]);
            uint32_t b0 = __float_as_uint(b.x), b1 = __float_as_uint(b.y);
            mma_tf32(&pr[4 * j],
                     __float_as_uint(acc[4 * t + 0]), __float_as_uint(acc[4 * t + 1]),
                     __float_as_uint(acc[4 * t + 2]), __float_as_uint(acc[4 * t + 3]), b0, b1);
            mma_tf32(&pr[32 + 4 * j],
                     __float_as_uint(acc[32 + 4 * t + 0]), __float_as_uint(acc[32 + 4 * t + 1]),
                     __float_as_uint(acc[32 + 4 * t + 2]), __float_as_uint(acc[32 + 4 * t + 3]), b0, b1);
        }
    }

    // ---- epilogue: (c0,c1)/(c2,c3) d-pairs -> sm[dp][2*px], conflict-free ----
    __syncthreads();   // K/V tiles dead for all warps
#pragma unroll
    for (int T = 0; T < 2; T++) {
#pragma unroll
        for (int j = 0; j < 8; j++) {
            int pxa = warp * 32 + 4 * gid + 2 * T;      // row gid of tile T
            int dp  = 4 * j + qid;                      // d = 2*dp, d+1
            *reinterpret_cast<float2*>(&sm[dp * EP2 + 2 * pxa]) =
                make_float2(pr[32 * T + 4 * j + 0], pr[32 * T + 4 * j + 1]);   // (px, d),(px, d+1)
            *reinterpret_cast<float2*>(&sm[dp * EP2 + 2 * (pxa + 1)]) =
                make_float2(pr[32 * T + 4 * j + 2], pr[32 * T + 4 * j + 3]);   // (px+1, d),(px+1, d+1)
        }
    }
    __syncthreads();

    // ---- read pass: float2 per lane (8B-aligned, bank 2dp+2*lane distinct
    //      per 16-lane phase), scalar coalesced residual + store ----
    {
        const float* fb = feature + nh * (DD * HW) + tile * 128;
        float*       ob = out     + nh * (DD * HW) + tile * 128;
#pragma unroll
        for (int i = 0; i < 8; i++) {
            const int dp = warp * 8 + i;
            const int d  = 2 * dp;
#pragma unroll
            for (int rep = 0; rep < 4; rep++) {
                const int px = 32 * rep + lane;
                float2 v = *reinterpret_cast<const float2*>(&sm[dp * EP2 + 2 * px]);
                ob[d * HW + px]       = fb[d * HW + px]       + v.x;
                ob[(d + 1) * HW + px] = fb[(d + 1) * HW + px] + v.y;
            }
        }
    }
}

// ============================================================================
extern "C" void kernel_launch(void* const* d_in, const int* in_sizes, int n_in,
                              void* d_out, int out_size) {
    const float* feature = (const float*)d_in[0];
    const float* token   = (const float*)d_in[1];
    const float* Wv      = (const float*)d_in[2];
    const float* bv      = (const float*)d_in[3];
    const float* Wk      = (const float*)d_in[4];
    const float* bk      = (const float*)d_in[5];
    float* out = (float*)d_out;

    vk_kernel<<<NB * CCH, 64>>>(token, Wv, bv, Wk, bk);
    attn_kernel<<<NB * NH * 128, 128>>>(feature, out);
}

// round 14
// speedup vs baseline: 1.0137x; 1.0137x over previous
#include <cuda_runtime.h>
#include <cstdint>

// Problem constants (fixed by reference setup_inputs)
#define NB  8      // batch
#define CCH 512    // channels
#define NH  8      // heads
#define DD  64     // head dim
#define LL  64     // token length
#define CTK 256    // token channels
#define HW  16384  // 128*128 pixels

#define EPAD 132   // epilogue buffer row stride (floats)

// Scratch (device globals — no allocations allowed).
// Stored PRE-SWIZZLED in the packed-pair rotated layout the attn kernel uses:
//   element (row, col) -> row*64 + 2*((4*(col>>3) + (col&3) + 4*row)&31) + ((col>>2)&1)
// g_k: row=l, col=d (K/8, tf32-rounded).  g_v: row=d, col=l (V, tf32-rounded).
__device__ __align__(16) float g_k[NB * CCH * LL];
__device__ __align__(16) float g_v[NB * CCH * LL];

__device__ __forceinline__ uint32_t f2tf32(float x) {
    uint32_t r;
    asm("cvt.rn.tf32.f32 %0, %1;" : "=r"(r) : "f"(x));
    return r;
}

// m16n8k8 tf32 HMMA (base-target instruction, works at compute_103)
__device__ __forceinline__ void mma_tf32(float* c,
                                         uint32_t a0, uint32_t a1, uint32_t a2, uint32_t a3,
                                         uint32_t b0, uint32_t b1) {
    asm volatile(
        "mma.sync.aligned.m16n8k8.row.col.f32.tf32.tf32.f32 "
        "{%0,%1,%2,%3}, {%4,%5,%6,%7}, {%8,%9}, {%0,%1,%2,%3};"
        : "+f"(c[0]), "+f"(c[1]), "+f"(c[2]), "+f"(c[3])
        : "r"(a0), "r"(a1), "r"(a2), "r"(a3), "r"(b0), "r"(b1));
}

// ============================================================================
// Kernel 1: fused V/K projections (1x1 conv, K=256). Measured-best structure;
// outputs written directly in the rotated packed-pair layout.
// Grid: 8*512 blocks, 64 threads (thread = l).
// ============================================================================
__global__ void vk_kernel(const float* __restrict__ token,
                          const float* __restrict__ Wv, const float* __restrict__ bv,
                          const float* __restrict__ Wk, const float* __restrict__ bk) {
    __shared__ float wv_s[CTK];
    __shared__ float wk_s[CTK];
    const int o = blockIdx.x & (CCH - 1);
    const int n = blockIdx.x >> 9;
    const int l = threadIdx.x;

#pragma unroll
    for (int i = 0; i < 4; i++) {
        wv_s[l + 64 * i] = Wv[o * CTK + l + 64 * i];
        wk_s[l + 64 * i] = Wk[o * CTK + l + 64 * i];
    }
    __syncthreads();

    const float* tok = token + n * (CTK * LL) + l;
    float av0 = 0.f, av1 = 0.f, ak0 = 0.f, ak1 = 0.f;
#pragma unroll 8
    for (int ct = 0; ct < CTK; ct += 2) {
        float t0 = tok[ct * LL];
        float t1 = tok[(ct + 1) * LL];
        av0 = fmaf(wv_s[ct],     t0, av0);
        ak0 = fmaf(wk_s[ct],     t0, ak0);
        av1 = fmaf(wv_s[ct + 1], t1, av1);
        ak1 = fmaf(wk_s[ct + 1], t1, ak1);
    }
    float av = av0 + av1 + bv[o];
    float ak = (ak0 + ak1 + bk[o]) * 0.125f;  // 1/sqrt(C/h) = 1/8

    const int h = o >> 6, d = o & 63;
    const int slice = (n * NH + h) * (DD * LL);
    const int ka = l * 64 + 2 * ((4 * (d >> 3) + (d & 3) + 4 * l) & 31) + ((d >> 2) & 1);
    const int va = d * 64 + 2 * ((4 * (l >> 3) + (l & 3) + 4 * d) & 31) + ((l >> 2) & 1);
    g_k[slice + ka] = __uint_as_float(f2tf32(ak));
    g_v[slice + va] = __uint_as_float(f2tf32(av));
}

// ============================================================================
// Kernel 2: mma.sync tf32 attention, M=32 per warp, one 128-px tile per CTA.
// R11 structure (measured best attn 152.6us) + register-pressure cut:
// after the coef remap, the T=1 coef tiles are parked in the dead ks region
// (same-thread float4 smem round-trip, conflict-free) so acc[32..63] dies
// before GEMM2 and pr[64] reuses those registers -> <=128 regs, 4 CTAs/SM.
// CTA = 128 threads = 128 pixels of one (n,h); grid = 64 * 128 = 8192.
// Pixel permutation: MMA row r <-> local px 2*(r&7)+(r>>3): Q frags = LDG.64,
// GEMM2 D-regs pair into float2 epilogue stores (bank-verified).
// ============================================================================
__global__ __launch_bounds__(128, 4)
void attn_kernel(const float* __restrict__ feature, float* __restrict__ out) {
    __shared__ __align__(16) float sm[64 * EPAD];   // K/V staging, coefbuf, epi buffer
    float* ks = sm;                                  // [64 l][64 d] rotated; coefbuf after GEMM1
    float* vs = sm + 4096;                           // [64 d][64 l] rotated

    const int tid  = threadIdx.x;
    const int lane = tid & 31;
    const int warp = tid >> 5;
    const int gid  = lane >> 2;   // fragment row group
    const int qid  = lane & 3;    // fragment col group
    const int nh   = blockIdx.x >> 7;
    const int tile = blockIdx.x & 127;

    // ---- stage K/V: plain float4 copy (layout already rotated in gmem) ----
    {
        const float4* gk4 = reinterpret_cast<const float4*>(g_k) + nh * 1024;
        const float4* gv4 = reinterpret_cast<const float4*>(g_v) + nh * 1024;
        float4* ks4 = reinterpret_cast<float4*>(ks);
        float4* vs4 = reinterpret_cast<float4*>(vs);
#pragma unroll
        for (int i = 0; i < 8; i++) {
            int idx = tid + 128 * i;
            ks4[idx] = gk4[idx];
            vs4[idx] = gv4[idx];
        }
    }

    const float* f = feature + nh * (DD * HW) + tile * 128 + warp * 32;
    const int rot = (qid + 4 * gid) & 31;

    __syncthreads();

    // ---- GEMM1: acc[2 m-tiles][8 n-tiles][4]; Q frags via LDG.64 (px perm) ----
    float acc[64];
#pragma unroll
    for (int i = 0; i < 64; i++) acc[i] = 0.f;
#pragma unroll
    for (int kt = 0; kt < 8; kt++) {
        uint32_t a[2][4];
#pragma unroll
        for (int T = 0; T < 2; T++) {
            // row gid <-> px 2gid, row gid+8 <-> px 2gid+1 (within 16-px tile T)
            float2 q0 = *reinterpret_cast<const float2*>(f + (8 * kt + qid) * HW + 16 * T + 2 * gid);
            float2 q1 = *reinterpret_cast<const float2*>(f + (8 * kt + qid + 4) * HW + 16 * T + 2 * gid);
            a[T][0] = f2tf32(q0.x);   // (row gid,   col qid)
            a[T][1] = f2tf32(q0.y);   // (row gid+8, col qid)
            a[T][2] = f2tf32(q1.x);   // (row gid,   col qid+4)
            a[T][3] = f2tf32(q1.y);   // (row gid+8, col qid+4)
        }
        const int c2 = (4 * kt + rot) & 31;
#pragma unroll
        for (int j = 0; j < 8; j++) {
            float2 b = *reinterpret_cast<const float2*>(&ks[(8 * j + gid) * 64 + 2 * c2]);
            uint32_t b0 = __float_as_uint(b.x), b1 = __float_as_uint(b.y);
            mma_tf32(&acc[4 * j],      a[0][0], a[0][1], a[0][2], a[0][3], b0, b1);
            mma_tf32(&acc[32 + 4 * j], a[1][0], a[1][1], a[1][2], a[1][3], b0, b1);
        }
    }

    // ---- softmax per m-tile (rows gid via c0/c1, gid+8 via c2/c3) ----
#pragma unroll
    for (int T = 0; T < 2; T++) {
        float* ac = acc + 32 * T;
        float m0 = -1e30f, m1 = -1e30f;
#pragma unroll
        for (int j = 0; j < 8; j++) {
            m0 = fmaxf(m0, fmaxf(ac[4 * j + 0], ac[4 * j + 1]));
            m1 = fmaxf(m1, fmaxf(ac[4 * j + 2], ac[4 * j + 3]));
        }
        m0 = fmaxf(m0, __shfl_xor_sync(0xffffffffu, m0, 1));
        m0 = fmaxf(m0, __shfl_xor_sync(0xffffffffu, m0, 2));
        m1 = fmaxf(m1, __shfl_xor_sync(0xffffffffu, m1, 1));
        m1 = fmaxf(m1, __shfl_xor_sync(0xffffffffu, m1, 2));
        float s0 = 0.f, s1 = 0.f;
#pragma unroll
        for (int j = 0; j < 8; j++) {
            ac[4 * j + 0] = __expf(ac[4 * j + 0] - m0); s0 += ac[4 * j + 0];
            ac[4 * j + 1] = __expf(ac[4 * j + 1] - m0); s0 += ac[4 * j + 1];
            ac[4 * j + 2] = __expf(ac[4 * j + 2] - m1); s1 += ac[4 * j + 2];
            ac[4 * j + 3] = __expf(ac[4 * j + 3] - m1); s1 += ac[4 * j + 3];
        }
        s0 += __shfl_xor_sync(0xffffffffu, s0, 1);
        s0 += __shfl_xor_sync(0xffffffffu, s0, 2);
        s1 += __shfl_xor_sync(0xffffffffu, s1, 1);
        s1 += __shfl_xor_sync(0xffffffffu, s1, 2);
        const float inv0 = __frcp_rn(s0);
        const float inv1 = __frcp_rn(s1);
#pragma unroll
        for (int j = 0; j < 8; j++) {
            ac[4 * j + 0] = __uint_as_float(f2tf32(ac[4 * j + 0] * inv0));
            ac[4 * j + 1] = __uint_as_float(f2tf32(ac[4 * j + 1] * inv0));
            ac[4 * j + 2] = __uint_as_float(f2tf32(ac[4 * j + 2] * inv1));
            ac[4 * j + 3] = __uint_as_float(f2tf32(ac[4 * j + 3] * inv1));
        }
    }

    // ---- remap coef D-frag -> A-frag in place (row-preserving; perm-safe) ----
    {
        const int s0 = 4 * gid + (qid >> 1);
        const int s1 = s0 + 2;
        const bool odd = qid & 1;
#pragma unroll
        for (int T = 0; T < 2; T++) {
            float* ac = acc + 32 * T;
#pragma unroll
            for (int t = 0; t < 8; t++) {
                float v0 = __shfl_sync(0xffffffffu, ac[4 * t + 0], s0);
                float v1 = __shfl_sync(0xffffffffu, ac[4 * t + 1], s0);
                float v2 = __shfl_sync(0xffffffffu, ac[4 * t + 2], s0);
                float v3 = __shfl_sync(0xffffffffu, ac[4 * t + 3], s0);
                float w0 = __shfl_sync(0xffffffffu, ac[4 * t + 0], s1);
                float w1 = __shfl_sync(0xffffffffu, ac[4 * t + 1], s1);
                float w2 = __shfl_sync(0xffffffffu, ac[4 * t + 2], s1);
                float w3 = __shfl_sync(0xffffffffu, ac[4 * t + 3], s1);
                ac[4 * t + 0] = odd ? v1 : v0;
                ac[4 * t + 1] = odd ? v3 : v2;
                ac[4 * t + 2] = odd ? w1 : w0;
                ac[4 * t + 3] = odd ? w3 : w2;
            }
        }
    }

    // ---- park T=1 coef tiles in dead ks region (same-thread round-trip) ----
    __syncthreads();   // all warps' GEMM1 ks reads complete before overwrite
    {
        float4* cb = reinterpret_cast<float4*>(ks) + warp * 256 + lane;
#pragma unroll
        for (int t = 0; t < 8; t++)
            cb[t * 32] = make_float4(acc[32 + 4 * t + 0], acc[32 + 4 * t + 1],
                                     acc[32 + 4 * t + 2], acc[32 + 4 * t + 3]);
    }

    // ---- GEMM2: pr[2][8 d-tiles][4] = coef * V^T  (T1 coef reloaded) ----
    float pr[64];
#pragma unroll
    for (int i = 0; i < 64; i++) pr[i] = 0.f;
    {
        const float4* cb = reinterpret_cast<const float4*>(ks) + warp * 256 + lane;
#pragma unroll
        for (int t = 0; t < 8; t++) {
            float4 cf = cb[t * 32];   // own thread's T1 coef tile t
            uint32_t c10 = __float_as_uint(cf.x), c11 = __float_as_uint(cf.y);
            uint32_t c12 = __float_as_uint(cf.z), c13 = __float_as_uint(cf.w);
            const int c2 = (4 * t + rot) & 31;
#pragma unroll
            for (int j = 0; j < 8; j++) {
                float2 b = *reinterpret_cast<const float2*>(&vs[(8 * j + gid) * 64 + 2 * c2]);
                uint32_t b0 = __float_as_uint(b.x), b1 = __float_as_uint(b.y);
                mma_tf32(&pr[4 * j],
                         __float_as_uint(acc[4 * t + 0]), __float_as_uint(acc[4 * t + 1]),
                         __float_as_uint(acc[4 * t + 2]), __float_as_uint(acc[4 * t + 3]), b0, b1);
                mma_tf32(&pr[32 + 4 * j], c10, c11, c12, c13, b0, b1);
            }
        }
    }

    // ---- epilogue: D-frags -> sm via STS.64 pairs, then coalesced pass ----
    __syncthreads();   // K/V tiles + coefbuf dead for all warps
#pragma unroll
    for (int T = 0; T < 2; T++) {
#pragma unroll
        for (int j = 0; j < 8; j++) {
            int px = warp * 32 + 16 * T + 2 * gid;   // (c0,c2) = px, px+1 at same d
            int d  = 8 * j + 2 * qid;
            *reinterpret_cast<float2*>(&sm[d * EPAD + px]) =
                make_float2(pr[32 * T + 4 * j + 0], pr[32 * T + 4 * j + 2]);
            *reinterpret_cast<float2*>(&sm[(d + 1) * EPAD + px]) =
                make_float2(pr[32 * T + 4 * j + 1], pr[32 * T + 4 * j + 3]);
        }
    }
    __syncthreads();

    {
        const float* fb = feature + nh * (DD * HW) + tile * 128;
        float*       ob = out     + nh * (DD * HW) + tile * 128;
        const int px4 = lane * 4;
#pragma unroll
        for (int i = 0; i < 16; i++) {
            int d = warp * 16 + i;
            float4 p  = *reinterpret_cast<const float4*>(&sm[d * EPAD + px4]);
            float4 fv = *reinterpret_cast<const float4*>(&fb[d * HW + px4]);
            float4 ov;
            ov.x = fv.x + p.x; ov.y = fv.y + p.y;
            ov.z = fv.z + p.z; ov.w = fv.w + p.w;
            *reinterpret_cast<float4*>(&ob[d * HW + px4]) = ov;
        }
    }
}

// ============================================================================
extern "C" void kernel_launch(void* const* d_in, const int* in_sizes, int n_in,
                              void* d_out, int out_size) {
    const float* feature = (const float*)d_in[0];
    const float* token   = (const float*)d_in[1];
    const float* Wv      = (const float*)d_in[2];
    const float* bv      = (const float*)d_in[3];
    const float* Wk      = (const float*)d_in[4];
    const float* bk      = (const float*)d_in[5];
    float* out = (float*)d_out;

    vk_kernel<<<NB * CCH, 64>>>(token, Wv, bv, Wk, bk);
    attn_kernel<<<NB * NH * 128, 128>>>(feature, out);
}

// round 15
// speedup vs baseline: 1.0534x; 1.0392x over previous
#include <cuda_runtime.h>
#include <cstdint>

// Problem constants (fixed by reference setup_inputs)
#define NB  8      // batch
#define CCH 512    // channels
#define NH  8      // heads
#define DD  64     // head dim
#define LL  64     // token length
#define CTK 256    // token channels
#define HW  16384  // 128*128 pixels

#define EPAD 132   // epilogue buffer row stride (floats)

// Scratch (device globals — no allocations allowed).
// Stored PRE-SWIZZLED in a QUAD-PACKED rotated layout:
//   element (row, col) -> row*64 + 4*((4*(col>>4) + (col&3) + 4*row) & 15) + ((col>>2)&3)
// One float4 at quad ((4*g + qid + 4*row)&15) holds cols {16g+qid, +4, +8, +12}
// = the B-fragments of k-tiles 2g and 2g+1 for thread column-group qid.
// g_k: row=l, col=d (K/8, tf32-rounded).  g_v: row=d, col=l (V, tf32-rounded).
__device__ __align__(16) float g_k[NB * CCH * LL];
__device__ __align__(16) float g_v[NB * CCH * LL];

__device__ __forceinline__ uint32_t f2tf32(float x) {
    uint32_t r;
    asm("cvt.rn.tf32.f32 %0, %1;" : "=r"(r) : "f"(x));
    return r;
}

// m16n8k8 tf32 HMMA (base-target instruction, works at compute_103)
__device__ __forceinline__ void mma_tf32(float* c,
                                         uint32_t a0, uint32_t a1, uint32_t a2, uint32_t a3,
                                         uint32_t b0, uint32_t b1) {
    asm volatile(
        "mma.sync.aligned.m16n8k8.row.col.f32.tf32.tf32.f32 "
        "{%0,%1,%2,%3}, {%4,%5,%6,%7}, {%8,%9}, {%0,%1,%2,%3};"
        : "+f"(c[0]), "+f"(c[1]), "+f"(c[2]), "+f"(c[3])
        : "r"(a0), "r"(a1), "r"(a2), "r"(a3), "r"(b0), "r"(b1));
}

// ============================================================================
// Kernel 1: fused V/K projections (1x1 conv, K=256). Measured-best structure;
// outputs written directly in the quad-packed rotated layout.
// Grid: 8*512 blocks, 64 threads (thread = l).
// ============================================================================
__global__ void vk_kernel(const float* __restrict__ token,
                          const float* __restrict__ Wv, const float* __restrict__ bv,
                          const float* __restrict__ Wk, const float* __restrict__ bk) {
    __shared__ float wv_s[CTK];
    __shared__ float wk_s[CTK];
    const int o = blockIdx.x & (CCH - 1);
    const int n = blockIdx.x >> 9;
    const int l = threadIdx.x;

#pragma unroll
    for (int i = 0; i < 4; i++) {
        wv_s[l + 64 * i] = Wv[o * CTK + l + 64 * i];
        wk_s[l + 64 * i] = Wk[o * CTK + l + 64 * i];
    }
    __syncthreads();

    const float* tok = token + n * (CTK * LL) + l;
    float av0 = 0.f, av1 = 0.f, ak0 = 0.f, ak1 = 0.f;
#pragma unroll 8
    for (int ct = 0; ct < CTK; ct += 2) {
        float t0 = tok[ct * LL];
        float t1 = tok[(ct + 1) * LL];
        av0 = fmaf(wv_s[ct],     t0, av0);
        ak0 = fmaf(wk_s[ct],     t0, ak0);
        av1 = fmaf(wv_s[ct + 1], t1, av1);
        ak1 = fmaf(wk_s[ct + 1], t1, ak1);
    }
    float av = av0 + av1 + bv[o];
    float ak = (ak0 + ak1 + bk[o]) * 0.125f;  // 1/sqrt(C/h) = 1/8

    const int h = o >> 6, d = o & 63;
    const int slice = (n * NH + h) * (DD * LL);
    // quad-packed rotated addresses
    const int ka = l * 64 + 4 * ((4 * (d >> 4) + (d & 3) + 4 * l) & 15) + ((d >> 2) & 3);
    const int va = d * 64 + 4 * ((4 * (l >> 4) + (l & 3) + 4 * d) & 15) + ((l >> 2) & 3);
    g_k[slice + ka] = __uint_as_float(f2tf32(ak));
    g_v[slice + va] = __uint_as_float(f2tf32(av));
}

// ============================================================================
// Kernel 2: mma.sync tf32 attention, M=32 per warp, one 128-px tile per CTA.
// R11 structure (measured best attn 152.6us) + instruction-count cuts:
//  - quad-packed B: one LDS.128 serves TWO k-tiles (B-LDS instrs halved)
//  - Q and coef fed to HMMA as raw fp32 bits (HW truncates to tf32; cvts gone)
// CTA = 128 threads = 128 pixels of one (n,h); grid = 64 * 128 = 8192.
// Pixel permutation: MMA row r <-> local px 2*(r&7)+(r>>3): Q frags = LDG.64,
// GEMM2 D-regs pair into float2 epilogue stores (bank-verified).
// ============================================================================
__global__ __launch_bounds__(128, 3)
void attn_kernel(const float* __restrict__ feature, float* __restrict__ out) {
    __shared__ __align__(16) float sm[64 * EPAD];   // K/V staging, then epi buffer
    float* ks = sm;                                  // [64 l][64 d] quad-pack rotated
    float* vs = sm + 4096;                           // [64 d][64 l] quad-pack rotated

    const int tid  = threadIdx.x;
    const int lane = tid & 31;
    const int warp = tid >> 5;
    const int gid  = lane >> 2;   // fragment row group
    const int qid  = lane & 3;    // fragment col group
    const int nh   = blockIdx.x >> 7;
    const int tile = blockIdx.x & 127;

    // ---- stage K/V: plain float4 copy (layout already packed in gmem) ----
    {
        const float4* gk4 = reinterpret_cast<const float4*>(g_k) + nh * 1024;
        const float4* gv4 = reinterpret_cast<const float4*>(g_v) + nh * 1024;
        float4* ks4 = reinterpret_cast<float4*>(ks);
        float4* vs4 = reinterpret_cast<float4*>(vs);
#pragma unroll
        for (int i = 0; i < 8; i++) {
            int idx = tid + 128 * i;
            ks4[idx] = gk4[idx];
            vs4[idx] = gv4[idx];
        }
    }

    const float* f = feature + nh * (DD * HW) + tile * 128 + warp * 32;
    const int qrot = (qid + 4 * gid) & 15;   // per-thread quad rotation base

    __syncthreads();

    // ---- GEMM1: acc[2 m-tiles][8 n-tiles][4]; Q via LDG.64 (px perm),
    //      B via one LDS.128 per (j, k-tile-pair) ----
    float acc[64];
#pragma unroll
    for (int i = 0; i < 64; i++) acc[i] = 0.f;
#pragma unroll
    for (int g = 0; g < 4; g++) {
        uint32_t a[2][2][4];   // [k-sub][T][frag]
#pragma unroll
        for (int kk = 0; kk < 2; kk++) {
            const int kt = 2 * g + kk;
#pragma unroll
            for (int T = 0; T < 2; T++) {
                // row gid <-> px 2gid, row gid+8 <-> px 2gid+1 (within 16-px tile T)
                float2 q0 = *reinterpret_cast<const float2*>(f + (8 * kt + qid) * HW + 16 * T + 2 * gid);
                float2 q1 = *reinterpret_cast<const float2*>(f + (8 * kt + qid + 4) * HW + 16 * T + 2 * gid);
                a[kk][T][0] = __float_as_uint(q0.x);   // raw bits; HMMA truncates to tf32
                a[kk][T][1] = __float_as_uint(q0.y);
                a[kk][T][2] = __float_as_uint(q1.x);
                a[kk][T][3] = __float_as_uint(q1.y);
            }
        }
        const int q4 = (4 * g + qrot) & 15;
#pragma unroll
        for (int j = 0; j < 8; j++) {
            float4 b = *reinterpret_cast<const float4*>(&ks[(8 * j + gid) * 64 + 4 * q4]);
            uint32_t bx = __float_as_uint(b.x), by = __float_as_uint(b.y);
            uint32_t bz = __float_as_uint(b.z), bw = __float_as_uint(b.w);
            mma_tf32(&acc[4 * j],      a[0][0][0], a[0][0][1], a[0][0][2], a[0][0][3], bx, by);
            mma_tf32(&acc[32 + 4 * j], a[0][1][0], a[0][1][1], a[0][1][2], a[0][1][3], bx, by);
            mma_tf32(&acc[4 * j],      a[1][0][0], a[1][0][1], a[1][0][2], a[1][0][3], bz, bw);
            mma_tf32(&acc[32 + 4 * j], a[1][1][0], a[1][1][1], a[1][1][2], a[1][1][3], bz, bw);
        }
    }

    // ---- softmax per m-tile (rows gid via c0/c1, gid+8 via c2/c3) ----
#pragma unroll
    for (int T = 0; T < 2; T++) {
        float* ac = acc + 32 * T;
        float m0 = -1e30f, m1 = -1e30f;
#pragma unroll
        for (int j = 0; j < 8; j++) {
            m0 = fmaxf(m0, fmaxf(ac[4 * j + 0], ac[4 * j + 1]));
            m1 = fmaxf(m1, fmaxf(ac[4 * j + 2], ac[4 * j + 3]));
        }
        m0 = fmaxf(m0, __shfl_xor_sync(0xffffffffu, m0, 1));
        m0 = fmaxf(m0, __shfl_xor_sync(0xffffffffu, m0, 2));
        m1 = fmaxf(m1, __shfl_xor_sync(0xffffffffu, m1, 1));
        m1 = fmaxf(m1, __shfl_xor_sync(0xffffffffu, m1, 2));
        float s0 = 0.f, s1 = 0.f;
#pragma unroll
        for (int j = 0; j < 8; j++) {
            ac[4 * j + 0] = __expf(ac[4 * j + 0] - m0); s0 += ac[4 * j + 0];
            ac[4 * j + 1] = __expf(ac[4 * j + 1] - m0); s0 += ac[4 * j + 1];
            ac[4 * j + 2] = __expf(ac[4 * j + 2] - m1); s1 += ac[4 * j + 2];
            ac[4 * j + 3] = __expf(ac[4 * j + 3] - m1); s1 += ac[4 * j + 3];
        }
        s0 += __shfl_xor_sync(0xffffffffu, s0, 1);
        s0 += __shfl_xor_sync(0xffffffffu, s0, 2);
        s1 += __shfl_xor_sync(0xffffffffu, s1, 1);
        s1 += __shfl_xor_sync(0xffffffffu, s1, 2);
        const float inv0 = __frcp_rn(s0);
        const float inv1 = __frcp_rn(s1);
#pragma unroll
        for (int j = 0; j < 8; j++) {
            ac[4 * j + 0] = ac[4 * j + 0] * inv0;   // raw bits; HMMA truncates
            ac[4 * j + 1] = ac[4 * j + 1] * inv0;
            ac[4 * j + 2] = ac[4 * j + 2] * inv1;
            ac[4 * j + 3] = ac[4 * j + 3] * inv1;
        }
    }

    // ---- remap coef D-frag -> A-frag in place (row-preserving; perm-safe) ----
    {
        const int s0 = 4 * gid + (qid >> 1);
        const int s1 = s0 + 2;
        const bool odd = qid & 1;
#pragma unroll
        for (int T = 0; T < 2; T++) {
            float* ac = acc + 32 * T;
#pragma unroll
            for (int t = 0; t < 8; t++) {
                float v0 = __shfl_sync(0xffffffffu, ac[4 * t + 0], s0);
                float v1 = __shfl_sync(0xffffffffu, ac[4 * t + 1], s0);
                float v2 = __shfl_sync(0xffffffffu, ac[4 * t + 2], s0);
                float v3 = __shfl_sync(0xffffffffu, ac[4 * t + 3], s0);
                float w0 = __shfl_sync(0xffffffffu, ac[4 * t + 0], s1);
                float w1 = __shfl_sync(0xffffffffu, ac[4 * t + 1], s1);
                float w2 = __shfl_sync(0xffffffffu, ac[4 * t + 2], s1);
                float w3 = __shfl_sync(0xffffffffu, ac[4 * t + 3], s1);
                ac[4 * t + 0] = odd ? v1 : v0;
                ac[4 * t + 1] = odd ? v3 : v2;
                ac[4 * t + 2] = odd ? w1 : w0;
                ac[4 * t + 3] = odd ? w3 : w2;
            }
        }
    }

    // ---- GEMM2: pr[2][8 d-tiles][4] = coef * V^T (quad-packed B) ----
    float pr[64];
#pragma unroll
    for (int i = 0; i < 64; i++) pr[i] = 0.f;
#pragma unroll
    for (int g = 0; g < 4; g++) {
        const int q4 = (4 * g + qrot) & 15;
        const int t0 = 2 * g, t1 = 2 * g + 1;
#pragma unroll
        for (int j = 0; j < 8; j++) {
            float4 b = *reinterpret_cast<const float4*>(&vs[(8 * j + gid) * 64 + 4 * q4]);
            uint32_t bx = __float_as_uint(b.x), by = __float_as_uint(b.y);
            uint32_t bz = __float_as_uint(b.z), bw = __float_as_uint(b.w);
            mma_tf32(&pr[4 * j],
                     __float_as_uint(acc[4 * t0 + 0]), __float_as_uint(acc[4 * t0 + 1]),
                     __float_as_uint(acc[4 * t0 + 2]), __float_as_uint(acc[4 * t0 + 3]), bx, by);
            mma_tf32(&pr[32 + 4 * j],
                     __float_as_uint(acc[32 + 4 * t0 + 0]), __float_as_uint(acc[32 + 4 * t0 + 1]),
                     __float_as_uint(acc[32 + 4 * t0 + 2]), __float_as_uint(acc[32 + 4 * t0 + 3]), bx, by);
            mma_tf32(&pr[4 * j],
                     __float_as_uint(acc[4 * t1 + 0]), __float_as_uint(acc[4 * t1 + 1]),
                     __float_as_uint(acc[4 * t1 + 2]), __float_as_uint(acc[4 * t1 + 3]), bz, bw);
            mma_tf32(&pr[32 + 4 * j],
                     __float_as_uint(acc[32 + 4 * t1 + 0]), __float_as_uint(acc[32 + 4 * t1 + 1]),
                     __float_as_uint(acc[32 + 4 * t1 + 2]), __float_as_uint(acc[32 + 4 * t1 + 3]), bz, bw);
        }
    }

    // ---- epilogue: D-frags -> sm via STS.64 pairs, then coalesced pass ----
    __syncthreads();   // K/V tiles dead for all warps
#pragma unroll
    for (int T = 0; T < 2; T++) {
#pragma unroll
        for (int j = 0; j < 8; j++) {
            int px = warp * 32 + 16 * T + 2 * gid;   // (c0,c2) = px, px+1 at same d
            int d  = 8 * j + 2 * qid;
            *reinterpret_cast<float2*>(&sm[d * EPAD + px]) =
                make_float2(pr[32 * T + 4 * j + 0], pr[32 * T + 4 * j + 2]);
            *reinterpret_cast<float2*>(&sm[(d + 1) * EPAD + px]) =
                make_float2(pr[32 * T + 4 * j + 1], pr[32 * T + 4 * j + 3]);
        }
    }
    __syncthreads();

    {
        const float* fb = feature + nh * (DD * HW) + tile * 128;
        float*       ob = out     + nh * (DD * HW) + tile * 128;
        const int px4 = lane * 4;
#pragma unroll
        for (int i = 0; i < 16; i++) {
            int d = warp * 16 + i;
            float4 p  = *reinterpret_cast<const float4*>(&sm[d * EPAD + px4]);
            float4 fv = *reinterpret_cast<const float4*>(&fb[d * HW + px4]);
            float4 ov;
            ov.x = fv.x + p.x; ov.y = fv.y + p.y;
            ov.z = fv.z + p.z; ov.w = fv.w + p.w;
            *reinterpret_cast<float4*>(&ob[d * HW + px4]) = ov;
        }
    }
}

// ============================================================================
extern "C" void kernel_launch(void* const* d_in, const int* in_sizes, int n_in,
                              void* d_out, int out_size) {
    const float* feature = (const float*)d_in[0];
    const float* token   = (const float*)d_in[1];
    const float* Wv      = (const float*)d_in[2];
    const float* bv      = (const float*)d_in[3];
    const float* Wk      = (const float*)d_in[4];
    const float* bk      = (const float*)d_in[5];
    float* out = (float*)d_out;

    vk_kernel<<<NB * CCH, 64>>>(token, Wv, bv, Wk, bk);
    attn_kernel<<<NB * NH * 128, 128>>>(feature, out);
}